// round 6
// baseline (speedup 1.0000x reference)
#include <cuda_runtime.h>
#include <cstdint>

#define NXG 100
#define NYG 100
#define NN  (NXG * NYG)                   // 10000 nodes
#define ROWBYTES (NN * 4)                 // 40000 B per row
#define ROWVEC (NN / 4)                   // 2500 float4 per row
#define ROWS_PER_BLOCK 8                  // 8 warps/block, 1 warp per row
#define ZBUF_BYTES 16384                  // SMEM zero source for bulk stores

__device__ __forceinline__ void stcs4(float4* p, float4 v) {
    asm volatile("st.global.cs.v4.f32 [%0], {%1, %2, %3, %4};"
                 :: "l"(p), "f"(v.x), "f"(v.y), "f"(v.z), "f"(v.w) : "memory");
}

__device__ __forceinline__ void bulk_store(void* gptr, uint32_t saddr, uint32_t nbytes) {
    asm volatile("cp.async.bulk.global.shared::cta.bulk_group [%0], [%1], %2;"
                 :: "l"(gptr), "r"(saddr), "r"(nbytes) : "memory");
}

__device__ __forceinline__ float pow125(float x) {
    return x * sqrtf(sqrtf(x));           // x^1.25, x > 0
}

__global__ void __launch_bounds__(256)
sgds_tma_kernel(const float* __restrict__ pot,
                const float* __restrict__ chan,
                const float* __restrict__ sheet,
                const float* __restrict__ face_len,
                const float* __restrict__ link_len,
                const int*   __restrict__ adj,
                const int*   __restrict__ lnk,
                const int*   __restrict__ face_at_link,
                const int*   __restrict__ head,
                const int*   __restrict__ tail,
                const int*   __restrict__ inout,
                float*       __restrict__ out)
{
    __shared__ __align__(128) float4 zbuf[ZBUF_BYTES / 16];

    const int tid  = threadIdx.x;
    const int lane = tid & 31;
    const int warp = tid >> 5;
    const int s    = lane & 3;            // slot (redundant across lane nibbles)
    const int i    = blockIdx.x * ROWS_PER_BLOCK + warp;   // row

    // ---- zero the SMEM bulk-store source ----
    const float4 z = make_float4(0.f, 0.f, 0.f, 0.f);
    #pragma unroll
    for (int k = tid; k < ZBUF_BYTES / 16; k += 256) zbuf[k] = z;
    __syncthreads();

    float* row   = out + (size_t)i * NN;
    float4* rowv = reinterpret_cast<float4*>(row);

    // nonzero window: columns [i-100, i+100] -> vectors [wlo, whi]
    const int wlo = (i >= 100 ? i - 100 : 0) >> 2;
    const int whi = ((i + 100 < NN) ? i + 100 : NN - 1) >> 2;

    // ---- issue async bulk zero-fill for prefix + suffix (lane 0 per warp) ----
    if (lane == 0) {
        asm volatile("fence.proxy.async.shared::cta;" ::: "memory");
        uint32_t zaddr = (uint32_t)__cvta_generic_to_shared(zbuf);
        char* gp = (char*)row;

        const uint32_t pre = (uint32_t)wlo * 16u;
        for (uint32_t off = 0; off < pre; off += ZBUF_BYTES) {
            uint32_t n = pre - off; if (n > ZBUF_BYTES) n = ZBUF_BYTES;
            bulk_store(gp + off, zaddr, n);
        }
        const uint32_t sufoff = (uint32_t)(whi + 1) * 16u;
        const uint32_t suf    = (uint32_t)ROWBYTES - sufoff;
        for (uint32_t off = 0; off < suf; off += ZBUF_BYTES) {
            uint32_t n = suf - off; if (n > ZBUF_BYTES) n = ZBUF_BYTES;
            bulk_store(gp + sufoff + off, zaddr, n);
        }
        asm volatile("cp.async.bulk.commit_group;" ::: "memory");
    }

    // ---- compute slot terms (overlapped with async copies) ----
    const int j_raw = adj[i * 4 + s];
    const int l_raw = lnk[i * 4 + s];
    const int io    = inout[i];

    const bool bnd   = (io == 1);
    const bool valid = (j_raw >= 0) && !bnd;

    const int jc = j_raw >= 0 ? j_raw : 0;
    const int lc = l_raw >= 0 ? l_raw : 0;

    const float ll  = link_len[lc];
    const int   h   = head[lc];
    const int   t   = tail[lc];
    const float cl  = chan[lc];
    const int   fal = face_at_link[lc];
    const float cj  = chan[jc];
    const float sj  = sheet[jc];
    const float ci  = chan[i];
    const float si  = sheet[i];

    const float ph  = pot[h];
    const float pt  = pot[t];
    const float sh  = sheet[h];
    const float stt = sheet[t];
    const float fl  = face_len[fal];

    const float K_SHEET = 0.01f;
    const float K_CHAN  = 0.1f;
    const float CAVSP   = 2.0f;
    const float DISS = (float)((1.0 / 917.0 - 1.0 / 1000.0) / 3.34e5);

    const float g  = (ph - pt) / ll;
    const float rg = rsqrtf(fabsf(g));                    // |g|^(-0.5)

    const float chan_q  = -K_CHAN * pow125(cl) * g;
    const float st_link = 0.5f * (sh + stt);
    const float sheet_q = -K_SHEET * pow125(st_link) * rg * g;

    const float cs = 0.5f * (ci + cj);                    // node-indexed (ref quirk)
    const float st = 0.5f * (si + sj);

    const float sheet_flux = -K_SHEET * pow125(st) * rg * fl / ll;
    const float chan_flux  = -K_CHAN  * pow125(cs) * fl / ll;
    const float ch_diss    = fabsf(DISS * chan_q * fl);
    const float sh_diss    = fabsf(DISS * sheet_q * CAVSP * fl);

    float term = valid ? (sheet_flux + chan_flux + ch_diss + sh_diss) : 0.0f;

    // diagonal = sum of the 4 slots (every nibble holds slots 0-3)
    float diag = term;
    diag += __shfl_xor_sync(0xFFFFFFFFu, diag, 1, 32);
    diag += __shfl_xor_sync(0xFFFFFFFFu, diag, 2, 32);
    if (bnd) diag = 1.0f;

    // broadcast (col, -term) of slots 0..3 to all lanes
    const int jcol = valid ? j_raw : -1;
    const int   c0 = __shfl_sync(0xFFFFFFFFu, jcol, 0);
    const int   c1 = __shfl_sync(0xFFFFFFFFu, jcol, 1);
    const int   c2 = __shfl_sync(0xFFFFFFFFu, jcol, 2);
    const int   c3 = __shfl_sync(0xFFFFFFFFu, jcol, 3);
    const float v0 = -__shfl_sync(0xFFFFFFFFu, term, 0);
    const float v1 = -__shfl_sync(0xFFFFFFFFu, term, 1);
    const float v2 = -__shfl_sync(0xFFFFFFFFu, term, 2);
    const float v3 = -__shfl_sync(0xFFFFFFFFu, term, 3);

    // ---- window: full-width stores with nonzeros selected in ----
    for (int w = wlo + lane; w <= whi; w += 32) {
        const int e = w * 4;
        float4 o;
        #pragma unroll
        for (int k = 0; k < 4; ++k) {
            const int c = e + k;
            float r = (c == i)  ? diag : 0.0f;
            r       = (c == c0) ? v0   : r;
            r       = (c == c1) ? v1   : r;
            r       = (c == c2) ? v2   : r;
            r       = (c == c3) ? v3   : r;
            (&o.x)[k] = r;
        }
        stcs4(rowv + w, o);
    }

    // ---- ensure bulk stores are complete before kernel exit ----
    if (lane == 0) {
        asm volatile("cp.async.bulk.wait_group 0;" ::: "memory");
    }
}

extern "C" void kernel_launch(void* const* d_in, const int* in_sizes, int n_in,
                              void* d_out, int out_size)
{
    const float* pot          = (const float*)d_in[0];
    const float* channel_size = (const float*)d_in[1];
    const float* sheet        = (const float*)d_in[2];
    const float* face_len     = (const float*)d_in[3];
    const float* link_len     = (const float*)d_in[4];
    const int*   adj          = (const int*)d_in[5];
    const int*   lnk          = (const int*)d_in[6];
    const int*   face_at_link = (const int*)d_in[7];
    const int*   head         = (const int*)d_in[8];
    const int*   tail         = (const int*)d_in[9];
    const int*   inout        = (const int*)d_in[10];

    float* out = (float*)d_out;

    sgds_tma_kernel<<<NN / ROWS_PER_BLOCK, 256>>>(pot, channel_size, sheet,
                                                  face_len, link_len, adj, lnk,
                                                  face_at_link, head, tail,
                                                  inout, out);
}